// round 15
// baseline (speedup 1.0000x reference)
#include <cuda_runtime.h>
#include <cuda_bf16.h>
#include <cstdint>

// Steerable encoder, fused single kernel, register-direct TF32 MMA,
// j-split CTAs (32 accumulators) + geometric exp recurrence, occupancy 3.
//   out_c[r][j] = sum_i (ey[r][i]*w_c[i]) * ex[j][i]
// Grid (3 ch x 2 j-halves x 72 K-splits) = 432 CTAs, co-resident at occ 3.

#define NA     128
#define NPIX   (NA * NA)
#define NPTS   8192
#define NSPLIT 72
#define KSTEPS 1024                // 8192 / 8 (k8 steps)
#define NCTAS  (6 * NSPLIT)        // 432 (<= 444 occ-3 residency)
#define MAXI   120                 // max i's per CTA (15 steps * 8)

__device__ float g_part[3 * NSPLIT * NPIX];       // 14.2 MB
__device__ unsigned int g_arrive  = 0;
__device__ unsigned int g_release = 0;

#define STEP   (4.0f / 127.0f)
#define KEXP   0.72134752044448170f        // 0.5*log2(e)
#define DELTA  (8.0f * STEP)               // fragment row/col spacing

// ---------------- helpers ----------------
__device__ __forceinline__ void mma_tf32(float* d, const uint32_t* a, const uint32_t* b) {
    asm volatile("mma.sync.aligned.m16n8k8.row.col.f32.tf32.tf32.f32 "
                 "{%0,%1,%2,%3}, {%4,%5,%6,%7}, {%8,%9}, {%0,%1,%2,%3};"
                 : "+f"(d[0]), "+f"(d[1]), "+f"(d[2]), "+f"(d[3])
                 : "r"(a[0]), "r"(a[1]), "r"(a[2]), "r"(a[3]), "r"(b[0]), "r"(b[1]));
}
__device__ __forceinline__ uint32_t cvt_tf32(float v) {
    uint32_t r;
    asm("cvt.rna.tf32.f32 %0, %1;" : "=r"(r) : "f"(v));
    return r;
}

// 4 Gaussian values at coords x0 + t*sgn*DELTA (t=0..3) vs point p:
//   e[t] = exp2(-KEXP*(x0 + t*sgn*DELTA - p)^2), via geometric recurrence.
__device__ __forceinline__ void exp_chain4(float d0, float c1, float q, float* e) {
    float e0 = exp2f(d0 * d0 * (-KEXP));
    float r0 = exp2f(fmaf(c1, d0, -KEXP * DELTA * DELTA));
    e[0] = e0;
    e[1] = e[0] * r0;  float r1 = r0 * q;
    e[2] = e[1] * r1;  float r2 = r1 * q;
    e[3] = e[2] * r2;
}

// ---------------- fused kernel ----------------
__global__ __launch_bounds__(256, 3)
void fused_kernel(const float* __restrict__ X, const float* __restrict__ Y,
                  float* __restrict__ out)
{
    __shared__ float spx[MAXI], spy[MAXI], sy0[MAXI], sy1[MAXI];
    __shared__ unsigned int sh_rel0;

    const int tid  = threadIdx.x;
    const int lane = tid & 31, wid = tid >> 5;
    const int c  = blockIdx.x % 3;              // channel
    const int jh = blockIdx.x / 3;              // j half (0/1)
    const int s  = blockIdx.y;                  // K split
    const int lo = (KSTEPS * s) / NSPLIT, hi = (KSTEPS * (s + 1)) / NSPLIT;
    const int cnt = (hi - lo) * 8;

    if (tid == 0) sh_rel0 = *(volatile unsigned int*)&g_release;

    // stage this CTA's point parameters
    for (int idx = tid; idx < cnt; idx += 256) {
        int i = lo * 8 + idx;
        float2 xp = ((const float2*)X)[i];
        float2 yp = ((const float2*)Y)[i];
        spx[idx] = xp.x; spy[idx] = xp.y;
        sy0[idx] = yp.x; sy1[idx] = yp.y;
    }

    const int wm = wid & 3, wn = wid >> 2;      // warp tile: rows [wm*32,+32), cols [wn*32,+32)
    const int gr = lane >> 2, tig = lane & 3;   // fragment lane coords

    // first row/col coordinate for this lane's chains
    const float y0 = 2.0f - (float)(wm * 32 + gr) * STEP;            // rows y0 - t*DELTA
    const float x0 = -2.0f + (float)(jh * 64 + wn * 32 + gr) * STEP; // cols x0 + t*DELTA
    const float q  = exp2f(-2.0f * KEXP * DELTA * DELTA);
    const float c1A =  2.0f * KEXP * DELTA;     // rows: spacing -DELTA
    const float c1B = -2.0f * KEXP * DELTA;     // cols: spacing +DELTA

    float acc[2][4][4];
    #pragma unroll
    for (int a = 0; a < 2; a++)
        #pragma unroll
        for (int b = 0; b < 4; b++)
            #pragma unroll
            for (int d = 0; d < 4; d++) acc[a][b][d] = 0.0f;

    __syncthreads();

    for (int ks = lo; ks < hi; ks++) {
        const int lb = (ks - lo) * 8;
        const int i0 = lb + tig, i1 = i0 + 4;   // lane's two k-slots

        const float px0 = spx[i0], px1 = spx[i1];
        const float py0 = spy[i0], py1 = spy[i1];
        float w0, w1;
        if (c == 0)      { w0 = 1.0f;    w1 = 1.0f;    }
        else if (c == 1) { w0 = sy0[i0]; w1 = sy0[i1]; }
        else             { w0 = sy1[i0]; w1 = sy1[i1]; }

        // ---- A chains: 4 row-values per point (rows gr+{0,8,16,24}) ----
        float ea0[4], ea1[4];
        exp_chain4(y0 - py0, c1A, q, ea0);
        exp_chain4(y0 - py1, c1A, q, ea1);
        uint32_t afr[2][4];
        #pragma unroll
        for (int mt = 0; mt < 2; mt++) {
            afr[mt][0] = cvt_tf32(ea0[2 * mt + 0] * w0);   // (row, k=tig)
            afr[mt][1] = cvt_tf32(ea0[2 * mt + 1] * w0);   // (row+8, k=tig)
            afr[mt][2] = cvt_tf32(ea1[2 * mt + 0] * w1);   // (row, k=tig+4)
            afr[mt][3] = cvt_tf32(ea1[2 * mt + 1] * w1);   // (row+8, k=tig+4)
        }

        // ---- B chains: 4 col-values per point (cols gr + nt*8) ----
        float eb0[4], eb1[4];
        exp_chain4(x0 - px0, c1B, q, eb0);
        exp_chain4(x0 - px1, c1B, q, eb1);

        #pragma unroll
        for (int nt = 0; nt < 4; nt++) {
            uint32_t bfr[2];
            bfr[0] = cvt_tf32(eb0[nt]);                    // (k=tig,   col)
            bfr[1] = cvt_tf32(eb1[nt]);                    // (k=tig+4, col)
            mma_tf32(acc[0][nt], afr[0], bfr);
            mma_tf32(acc[1][nt], afr[1], bfr);
        }
    }

    // ---- write partial plane [c][s][r][j] ----
    float* plane = g_part + (c * NSPLIT + s) * NPIX;
    #pragma unroll
    for (int mt = 0; mt < 2; mt++) {
        #pragma unroll
        for (int nt = 0; nt < 4; nt++) {
            int m0 = wm * 32 + mt * 16 + gr;
            int j0 = jh * 64 + wn * 32 + nt * 8 + 2 * tig;
            *(float2*)(plane + m0 * NA + j0)       = make_float2(acc[mt][nt][0], acc[mt][nt][1]);
            *(float2*)(plane + (m0 + 8) * NA + j0) = make_float2(acc[mt][nt][2], acc[mt][nt][3]);
        }
    }

    // ---- grid barrier (all 432 CTAs co-resident at occ 3) ----
    __threadfence();
    __syncthreads();
    if (tid == 0) {
        unsigned int old = atomicAdd(&g_arrive, 1u);
        if (old == NCTAS - 1) {
            g_arrive = 0;
            __threadfence();
            atomicAdd(&g_release, 1u);
        }
        while (*(volatile unsigned int*)&g_release == sh_rel0) { }
    }
    __syncthreads();
    __threadfence();

    // ---- fused reduce + normalize (partials L2-hot) ----
    const int bid = blockIdx.y * gridDim.x + blockIdx.x;    // 0..431
    const int p = bid * 256 + tid;
    if (p < NPIX) {
        float s0 = 0.0f, s1 = 0.0f, s2 = 0.0f;
        #pragma unroll 8
        for (int sl = 0; sl < NSPLIT; sl++) {
            s0 += __ldcg(&g_part[(0 * NSPLIT + sl) * NPIX + p]);
            s1 += __ldcg(&g_part[(1 * NSPLIT + sl) * NPIX + p]);
            s2 += __ldcg(&g_part[(2 * NSPLIT + sl) * NPIX + p]);
        }
        float r = 1.0f / s0;
        out[p]            = s0;
        out[NPIX + p]     = s1 * r;
        out[2 * NPIX + p] = s2 * r;
    }
}

extern "C" void kernel_launch(void* const* d_in, const int* in_sizes, int n_in,
                              void* d_out, int out_size)
{
    const float* X = (const float*)d_in[0];
    const float* Y = (const float*)d_in[1];
    float* out = (float*)d_out;

    fused_kernel<<<dim3(6, NSPLIT), 256>>>(X, Y, out);
}

// round 16
// speedup vs baseline: 1.0137x; 1.0137x over previous
#include <cuda_runtime.h>
#include <cuda_bf16.h>
#include <cstdint>

// Steerable encoder, fused single kernel, register-direct TF32 MMA,
// j-split CTAs (32 accumulators), geometric exp recurrence with raw
// MUFU ex2.approx (the libm exp2f software path was the R12-R15 bottleneck).
//   out_c[r][j] = sum_i (ey[r][i]*w_c[i]) * ex[j][i]
// Grid (3 ch x 2 j-halves x 72 K-splits) = 432 CTAs, co-resident at occ 3.

#define NA     128
#define NPIX   (NA * NA)
#define NPTS   8192
#define NSPLIT 72
#define KSTEPS 1024                // 8192 / 8 (k8 steps)
#define NCTAS  (6 * NSPLIT)        // 432 (<= 444 occ-3 residency)
#define MAXI   120                 // max i's per CTA (15 steps * 8)

__device__ float g_part[3 * NSPLIT * NPIX];       // 14.2 MB
__device__ unsigned int g_arrive  = 0;
__device__ unsigned int g_release = 0;

#define STEP   (4.0f / 127.0f)
#define KEXP   0.72134752044448170f        // 0.5*log2(e)
#define DELTA  (8.0f * STEP)               // fragment row/col spacing
#define QCONST 0.93848425f                 // e^{-DELTA^2} = 2^{-2*KEXP*DELTA^2}

// ---------------- helpers ----------------
__device__ __forceinline__ void mma_tf32(float* d, const uint32_t* a, const uint32_t* b) {
    asm volatile("mma.sync.aligned.m16n8k8.row.col.f32.tf32.tf32.f32 "
                 "{%0,%1,%2,%3}, {%4,%5,%6,%7}, {%8,%9}, {%0,%1,%2,%3};"
                 : "+f"(d[0]), "+f"(d[1]), "+f"(d[2]), "+f"(d[3])
                 : "r"(a[0]), "r"(a[1]), "r"(a[2]), "r"(a[3]), "r"(b[0]), "r"(b[1]));
}
__device__ __forceinline__ uint32_t cvt_tf32(float v) {
    uint32_t r;
    asm("cvt.rna.tf32.f32 %0, %1;" : "=r"(r) : "f"(v));
    return r;
}
__device__ __forceinline__ float ex2(float x) {      // MUFU.EX2, one op
    float r;
    asm("ex2.approx.ftz.f32 %0, %1;" : "=f"(r) : "f"(x));
    return r;
}

// 4 Gaussian values at coords x0 + t*sgn*DELTA (t=0..3) vs point p:
//   e[t] = 2^(-KEXP*(x0 + t*sgn*DELTA - p)^2), via geometric recurrence.
__device__ __forceinline__ void exp_chain4(float d0, float c1, float* e) {
    float e0 = ex2(d0 * d0 * (-KEXP));
    float r0 = ex2(fmaf(c1, d0, -KEXP * DELTA * DELTA));
    e[0] = e0;
    e[1] = e[0] * r0;  float r1 = r0 * QCONST;
    e[2] = e[1] * r1;  float r2 = r1 * QCONST;
    e[3] = e[2] * r2;
}

// ---------------- fused kernel ----------------
__global__ __launch_bounds__(256, 3)
void fused_kernel(const float* __restrict__ X, const float* __restrict__ Y,
                  float* __restrict__ out)
{
    __shared__ float spx[MAXI], spy[MAXI], sy0[MAXI], sy1[MAXI];
    __shared__ unsigned int sh_rel0;

    const int tid  = threadIdx.x;
    const int lane = tid & 31, wid = tid >> 5;
    const int c  = blockIdx.x % 3;              // channel
    const int jh = blockIdx.x / 3;              // j half (0/1)
    const int s  = blockIdx.y;                  // K split
    const int lo = (KSTEPS * s) / NSPLIT, hi = (KSTEPS * (s + 1)) / NSPLIT;
    const int cnt = (hi - lo) * 8;

    if (tid == 0) sh_rel0 = *(volatile unsigned int*)&g_release;

    // stage this CTA's point parameters
    for (int idx = tid; idx < cnt; idx += 256) {
        int i = lo * 8 + idx;
        float2 xp = ((const float2*)X)[i];
        float2 yp = ((const float2*)Y)[i];
        spx[idx] = xp.x; spy[idx] = xp.y;
        sy0[idx] = yp.x; sy1[idx] = yp.y;
    }

    const int wm = wid & 3, wn = wid >> 2;      // warp tile: rows [wm*32,+32), cols [wn*32,+32)
    const int gr = lane >> 2, tig = lane & 3;   // fragment lane coords

    // first row/col coordinate for this lane's chains
    const float y0 = 2.0f - (float)(wm * 32 + gr) * STEP;            // rows y0 - t*DELTA
    const float x0 = -2.0f + (float)(jh * 64 + wn * 32 + gr) * STEP; // cols x0 + t*DELTA
    const float c1A =  2.0f * KEXP * DELTA;     // rows: spacing -DELTA
    const float c1B = -2.0f * KEXP * DELTA;     // cols: spacing +DELTA

    float acc[2][4][4];
    #pragma unroll
    for (int a = 0; a < 2; a++)
        #pragma unroll
        for (int b = 0; b < 4; b++)
            #pragma unroll
            for (int d = 0; d < 4; d++) acc[a][b][d] = 0.0f;

    __syncthreads();

    for (int ks = lo; ks < hi; ks++) {
        const int lb = (ks - lo) * 8;
        const int i0 = lb + tig, i1 = i0 + 4;   // lane's two k-slots

        const float px0 = spx[i0], px1 = spx[i1];
        const float py0 = spy[i0], py1 = spy[i1];
        float w0, w1;
        if (c == 0)      { w0 = 1.0f;    w1 = 1.0f;    }
        else if (c == 1) { w0 = sy0[i0]; w1 = sy0[i1]; }
        else             { w0 = sy1[i0]; w1 = sy1[i1]; }

        // ---- A chains: 4 row-values per point (rows gr+{0,8,16,24}) ----
        float ea0[4], ea1[4];
        exp_chain4(y0 - py0, c1A, ea0);
        exp_chain4(y0 - py1, c1A, ea1);
        uint32_t afr[2][4];
        #pragma unroll
        for (int mt = 0; mt < 2; mt++) {
            afr[mt][0] = cvt_tf32(ea0[2 * mt + 0] * w0);   // (row, k=tig)
            afr[mt][1] = cvt_tf32(ea0[2 * mt + 1] * w0);   // (row+8, k=tig)
            afr[mt][2] = cvt_tf32(ea1[2 * mt + 0] * w1);   // (row, k=tig+4)
            afr[mt][3] = cvt_tf32(ea1[2 * mt + 1] * w1);   // (row+8, k=tig+4)
        }

        // ---- B chains: 4 col-values per point (cols gr + nt*8) ----
        float eb0[4], eb1[4];
        exp_chain4(x0 - px0, c1B, eb0);
        exp_chain4(x0 - px1, c1B, eb1);

        #pragma unroll
        for (int nt = 0; nt < 4; nt++) {
            uint32_t bfr[2];
            bfr[0] = cvt_tf32(eb0[nt]);                    // (k=tig,   col)
            bfr[1] = cvt_tf32(eb1[nt]);                    // (k=tig+4, col)
            mma_tf32(acc[0][nt], afr[0], bfr);
            mma_tf32(acc[1][nt], afr[1], bfr);
        }
    }

    // ---- write partial plane [c][s][r][j] ----
    float* plane = g_part + (c * NSPLIT + s) * NPIX;
    #pragma unroll
    for (int mt = 0; mt < 2; mt++) {
        #pragma unroll
        for (int nt = 0; nt < 4; nt++) {
            int m0 = wm * 32 + mt * 16 + gr;
            int j0 = jh * 64 + wn * 32 + nt * 8 + 2 * tig;
            *(float2*)(plane + m0 * NA + j0)       = make_float2(acc[mt][nt][0], acc[mt][nt][1]);
            *(float2*)(plane + (m0 + 8) * NA + j0) = make_float2(acc[mt][nt][2], acc[mt][nt][3]);
        }
    }

    // ---- grid barrier (all 432 CTAs co-resident at occ 3) ----
    __threadfence();
    __syncthreads();
    if (tid == 0) {
        unsigned int old = atomicAdd(&g_arrive, 1u);
        if (old == NCTAS - 1) {
            g_arrive = 0;
            __threadfence();
            atomicAdd(&g_release, 1u);
        }
        while (*(volatile unsigned int*)&g_release == sh_rel0) { }
    }
    __syncthreads();
    __threadfence();

    // ---- fused reduce + normalize (partials L2-hot) ----
    const int bid = blockIdx.y * gridDim.x + blockIdx.x;    // 0..431
    const int p = bid * 256 + tid;
    if (p < NPIX) {
        float s0 = 0.0f, s1 = 0.0f, s2 = 0.0f;
        #pragma unroll 8
        for (int sl = 0; sl < NSPLIT; sl++) {
            s0 += __ldcg(&g_part[(0 * NSPLIT + sl) * NPIX + p]);
            s1 += __ldcg(&g_part[(1 * NSPLIT + sl) * NPIX + p]);
            s2 += __ldcg(&g_part[(2 * NSPLIT + sl) * NPIX + p]);
        }
        float r = 1.0f / s0;
        out[p]            = s0;
        out[NPIX + p]     = s1 * r;
        out[2 * NPIX + p] = s2 * r;
    }
}

extern "C" void kernel_launch(void* const* d_in, const int* in_sizes, int n_in,
                              void* d_out, int out_size)
{
    const float* X = (const float*)d_in[0];
    const float* Y = (const float*)d_in[1];
    float* out = (float*)d_out;

    fused_kernel<<<dim3(6, NSPLIT), 256>>>(X, Y, out);
}

// round 17
// speedup vs baseline: 1.0473x; 1.0331x over previous
#include <cuda_runtime.h>
#include <cuda_bf16.h>
#include <cstdint>

// Steerable encoder, fused single kernel, register-direct TF32 MMA,
// ALL 3 CHANNELS MERGED per CTA (ey/ex exp chains computed once, shared):
//   out_c[r][j] = sum_i (ey[r][i]*w_c[i]) * ex[j][i]
// CTA tile: 128 rows x 32 cols, warp tile 32x16, 48 accumulators/thread.
// Grid (4 j-quarters x 74 K-splits) = 296 CTAs, co-resident at occ 2.

#define NA     128
#define NPIX   (NA * NA)
#define NPTS   8192
#define NSPLIT 74
#define KSTEPS 1024                // 8192 / 8 (k8 steps)
#define NCTAS  (4 * NSPLIT)        // 296 (= 148*2 occ-2 residency)
#define MAXI   120                 // max i's per CTA (14 steps * 8)

__device__ float g_part[3 * NSPLIT * NPIX];       // 14.5 MB
__device__ unsigned int g_arrive  = 0;
__device__ unsigned int g_release = 0;

#define STEP   (4.0f / 127.0f)
#define KEXP   0.72134752044448170f        // 0.5*log2(e)
#define DELTA  (8.0f * STEP)               // fragment row/col spacing
#define QCONST 0.93848425f                 // 2^{-2*KEXP*DELTA^2}

// ---------------- helpers ----------------
__device__ __forceinline__ void mma_tf32(float* d, const uint32_t* a, const uint32_t* b) {
    asm volatile("mma.sync.aligned.m16n8k8.row.col.f32.tf32.tf32.f32 "
                 "{%0,%1,%2,%3}, {%4,%5,%6,%7}, {%8,%9}, {%0,%1,%2,%3};"
                 : "+f"(d[0]), "+f"(d[1]), "+f"(d[2]), "+f"(d[3])
                 : "r"(a[0]), "r"(a[1]), "r"(a[2]), "r"(a[3]), "r"(b[0]), "r"(b[1]));
}
__device__ __forceinline__ uint32_t cvt_tf32(float v) {
    uint32_t r;
    asm("cvt.rna.tf32.f32 %0, %1;" : "=r"(r) : "f"(v));
    return r;
}
__device__ __forceinline__ float ex2(float x) {
    float r;
    asm("ex2.approx.ftz.f32 %0, %1;" : "=f"(r) : "f"(x));
    return r;
}

// 4 Gaussian values at coords x0 + t*sgn*DELTA (t=0..3) vs point p.
__device__ __forceinline__ void exp_chain4(float d0, float c1, float* e) {
    float e0 = ex2(d0 * d0 * (-KEXP));
    float r0 = ex2(fmaf(c1, d0, -KEXP * DELTA * DELTA));
    e[0] = e0;
    e[1] = e[0] * r0;  float r1 = r0 * QCONST;
    e[2] = e[1] * r1;  float r2 = r1 * QCONST;
    e[3] = e[2] * r2;
}
// 2 values (cols gr, gr+8).
__device__ __forceinline__ void exp_chain2(float d0, float c1, float* e) {
    float e0 = ex2(d0 * d0 * (-KEXP));
    float r0 = ex2(fmaf(c1, d0, -KEXP * DELTA * DELTA));
    e[0] = e0;
    e[1] = e0 * r0;
}

// ---------------- fused kernel ----------------
__global__ __launch_bounds__(256, 2)
void fused_kernel(const float* __restrict__ X, const float* __restrict__ Y,
                  float* __restrict__ out)
{
    __shared__ float spx[MAXI], spy[MAXI], sy0[MAXI], sy1[MAXI];
    __shared__ unsigned int sh_rel0;

    const int tid  = threadIdx.x;
    const int lane = tid & 31, wid = tid >> 5;
    const int jq = blockIdx.x;                  // j quarter (0..3)
    const int s  = blockIdx.y;                  // K split (0..73)
    const int lo = (KSTEPS * s) / NSPLIT, hi = (KSTEPS * (s + 1)) / NSPLIT;
    const int cnt = (hi - lo) * 8;

    if (tid == 0) sh_rel0 = *(volatile unsigned int*)&g_release;

    // stage this CTA's point parameters
    for (int idx = tid; idx < cnt; idx += 256) {
        int i = lo * 8 + idx;
        float2 xp = ((const float2*)X)[i];
        float2 yp = ((const float2*)Y)[i];
        spx[idx] = xp.x; spy[idx] = xp.y;
        sy0[idx] = yp.x; sy1[idx] = yp.y;
    }

    const int wm = wid & 3, wn = wid >> 2;      // warp tile: rows [wm*32,+32), cols [wn*16,+16)
    const int gr = lane >> 2, tig = lane & 3;   // fragment lane coords

    const float y0 = 2.0f - (float)(wm * 32 + gr) * STEP;                  // rows: y0 - t*DELTA
    const float x0 = -2.0f + (float)(jq * 32 + wn * 16 + gr) * STEP;       // cols: x0 + t*DELTA
    const float c1A =  2.0f * KEXP * DELTA;
    const float c1B = -2.0f * KEXP * DELTA;

    // acc[ch][mt][nt][4]
    float acc[3][2][2][4];
    #pragma unroll
    for (int a = 0; a < 3; a++)
        #pragma unroll
        for (int b = 0; b < 2; b++)
            #pragma unroll
            for (int d = 0; d < 2; d++)
                #pragma unroll
                for (int e = 0; e < 4; e++) acc[a][b][d][e] = 0.0f;

    __syncthreads();

    for (int ks = lo; ks < hi; ks++) {
        const int lb = (ks - lo) * 8;
        const int i0 = lb + tig, i1 = i0 + 4;   // lane's two k-slots

        const float px0 = spx[i0], px1 = spx[i1];
        const float py0 = spy[i0], py1 = spy[i1];
        const float wa0 = sy0[i0], wa1 = sy0[i1];
        const float wb0 = sy1[i0], wb1 = sy1[i1];

        // ---- shared ey chains (rows gr+{0,8,16,24}) ----
        float ea0[4], ea1[4];
        exp_chain4(y0 - py0, c1A, ea0);
        exp_chain4(y0 - py1, c1A, ea1);

        // ---- shared ex chains (cols gr, gr+8) ----
        float eb0[2], eb1[2];
        exp_chain2(x0 - px0, c1B, eb0);
        exp_chain2(x0 - px1, c1B, eb1);
        uint32_t bfr[2][2];
        #pragma unroll
        for (int nt = 0; nt < 2; nt++) {
            bfr[nt][0] = cvt_tf32(eb0[nt]);
            bfr[nt][1] = cvt_tf32(eb1[nt]);
        }

        // ---- per-channel A fragments + MMAs ----
        #pragma unroll
        for (int ch = 0; ch < 3; ch++) {
            float w0, w1;
            if (ch == 0)      { w0 = 1.0f; w1 = 1.0f; }
            else if (ch == 1) { w0 = wa0;  w1 = wa1;  }
            else              { w0 = wb0;  w1 = wb1;  }
            #pragma unroll
            for (int mt = 0; mt < 2; mt++) {
                uint32_t afr[4];
                if (ch == 0) {
                    afr[0] = cvt_tf32(ea0[2 * mt + 0]);
                    afr[1] = cvt_tf32(ea0[2 * mt + 1]);
                    afr[2] = cvt_tf32(ea1[2 * mt + 0]);
                    afr[3] = cvt_tf32(ea1[2 * mt + 1]);
                } else {
                    afr[0] = cvt_tf32(ea0[2 * mt + 0] * w0);
                    afr[1] = cvt_tf32(ea0[2 * mt + 1] * w0);
                    afr[2] = cvt_tf32(ea1[2 * mt + 0] * w1);
                    afr[3] = cvt_tf32(ea1[2 * mt + 1] * w1);
                }
                mma_tf32(acc[ch][mt][0], afr, bfr[0]);
                mma_tf32(acc[ch][mt][1], afr, bfr[1]);
            }
        }
    }

    // ---- write partial planes [ch][s][r][j] ----
    #pragma unroll
    for (int ch = 0; ch < 3; ch++) {
        float* plane = g_part + (ch * NSPLIT + s) * NPIX;
        #pragma unroll
        for (int mt = 0; mt < 2; mt++) {
            #pragma unroll
            for (int nt = 0; nt < 2; nt++) {
                int m0 = wm * 32 + mt * 16 + gr;
                int j0 = jq * 32 + wn * 16 + nt * 8 + 2 * tig;
                *(float2*)(plane + m0 * NA + j0) =
                    make_float2(acc[ch][mt][nt][0], acc[ch][mt][nt][1]);
                *(float2*)(plane + (m0 + 8) * NA + j0) =
                    make_float2(acc[ch][mt][nt][2], acc[ch][mt][nt][3]);
            }
        }
    }

    // ---- grid barrier (all 296 CTAs co-resident at occ 2) ----
    __threadfence();
    __syncthreads();
    if (tid == 0) {
        unsigned int old = atomicAdd(&g_arrive, 1u);
        if (old == NCTAS - 1) {
            g_arrive = 0;
            __threadfence();
            atomicAdd(&g_release, 1u);
        }
        while (*(volatile unsigned int*)&g_release == sh_rel0) { }
    }
    __syncthreads();
    __threadfence();

    // ---- fused reduce + normalize (partials L2-hot) ----
    const int bid = blockIdx.y * gridDim.x + blockIdx.x;    // 0..295
    const int p = bid * 256 + tid;
    if (p < NPIX) {
        float s0 = 0.0f, s1 = 0.0f, s2 = 0.0f;
        #pragma unroll 8
        for (int sl = 0; sl < NSPLIT; sl++) {
            s0 += __ldcg(&g_part[(0 * NSPLIT + sl) * NPIX + p]);
            s1 += __ldcg(&g_part[(1 * NSPLIT + sl) * NPIX + p]);
            s2 += __ldcg(&g_part[(2 * NSPLIT + sl) * NPIX + p]);
        }
        float r = 1.0f / s0;
        out[p]            = s0;
        out[NPIX + p]     = s1 * r;
        out[2 * NPIX + p] = s2 * r;
    }
}

extern "C" void kernel_launch(void* const* d_in, const int* in_sizes, int n_in,
                              void* d_out, int out_size)
{
    const float* X = (const float*)d_in[0];
    const float* Y = (const float*)d_in[1];
    float* out = (float*)d_out;

    fused_kernel<<<dim3(4, NSPLIT), 256>>>(X, Y, out);
}